// round 15
// baseline (speedup 1.0000x reference)
#include <cuda_runtime.h>
#include <math.h>

#define NT 512
#define NB 32
#define HF 128
#define NH 256

__device__ __align__(16) float g_feat[3][NB][NT][HF];
__device__ unsigned char g_mask[3][NB][NT];
__device__ __align__(16) float g_S[2][NB][NT][NT];
__device__ float g_rmax[2][NB][NT], g_rsum[2][NB][NT];
__device__ float g_cmax[2][NB][NT], g_csum[2][NB][NT];
__device__ __align__(16) float g_X[128][NT][NH];
__device__ __align__(16) float g_G[NT][1024][128];
__device__ __align__(16) float g_H[2][NH][128];
__device__ __align__(16) float g_Hsel[NH][128];
__device__ int g_lens[128], g_map[128], g_slotOf[128];
__device__ __align__(128) unsigned int g_cnt8[8][32];
__device__ unsigned int g_tdone[NT];   // per-t ingate completion counters (target 16)

__device__ __forceinline__ float fsig(float x) { return 1.f / (1.f + __expf(-x)); }
__device__ __forceinline__ float ftanh(float x) { return 2.f / (1.f + __expf(-2.f * x)) - 1.f; }

__global__ void k_prep(const int* la, const int* lt, const int* ln) {
    __shared__ int sl[128], si[128];
    int i = threadIdx.x, l = i >> 5, b = i & 31;
    int len = (l == 1) ? lt[b] : (l == 3) ? ln[b] : la[b];
    sl[i] = len; si[i] = i;
    __syncthreads();
    if (i == 0) {
        for (int a = 1; a < 128; a++) {
            int lv = sl[a], iv = si[a], c = a - 1;
            while (c >= 0 && sl[c] > lv) { sl[c+1]=sl[c]; si[c+1]=si[c]; c--; }
            sl[c+1]=lv; si[c+1]=iv;
        }
        for (int q = 0; q < 8; q++) g_cnt8[q][0] = 0u;
    }
    __syncthreads();
    g_lens[i] = sl[i]; g_map[i] = si[i]; g_slotOf[si[i]] = i;
    for (int q = i; q < NT; q += 128) g_tdone[q] = 0u;
}

__global__ void k_feat(const float* A, const float* T_, const float* N_,
                       const float* Wm, const float* bm) {
    int t = blockIdx.x, b = blockIdx.y, tr = blockIdx.z, j = threadIdx.x;
    const float* base = tr==0 ? A : (tr==1 ? T_ : N_);
    const float* x = base + ((size_t)b*NT + t)*4;
    float v = x[0]*Wm[2*j] + x[1]*Wm[2*j+1] + bm[j];
    float fv = v >= 0.f ? v : 0.1f*v;
    g_feat[tr][b][t][j] = fv;
    if (tr == 0) {
        g_X[g_slotOf[b]][t][j] = fv;
        g_X[g_slotOf[64 + b]][t][j] = fv;
    } else if (tr == 1) {
        g_X[g_slotOf[32 + b]][t][j] = fv;
    } else {
        g_X[g_slotOf[96 + b]][t][j] = fv;
    }
    if (j == 0) g_mask[tr][b][t] = (x[3]*128.f + x[2] - 257.f) > 0.5f ? 1 : 0;
}

__global__ void k_scores() {
    int z = blockIdx.z, pair = z >> 5, b = z & 31;
    int t0 = blockIdx.x*64, s0 = blockIdx.y*64;
    __shared__ __align__(16) float As[16][68], Bs[16][68];
    int tid = threadIdx.x, lrow = tid>>2, lq = tid&3, tx = tid&15, ty = tid>>4;
    float acc[4][4] = {};
    const float* A = &g_feat[0][b][0][0];
    const float* Bf = &g_feat[1+pair][b][0][0];
    for (int k0 = 0; k0 < HF; k0 += 16) {
        float4 a4 = *(const float4*)(A + (size_t)(t0+lrow)*HF + k0 + lq*4);
        float4 b4 = *(const float4*)(Bf + (size_t)(s0+lrow)*HF + k0 + lq*4);
        As[lq*4+0][lrow]=a4.x; As[lq*4+1][lrow]=a4.y; As[lq*4+2][lrow]=a4.z; As[lq*4+3][lrow]=a4.w;
        Bs[lq*4+0][lrow]=b4.x; Bs[lq*4+1][lrow]=b4.y; Bs[lq*4+2][lrow]=b4.z; Bs[lq*4+3][lrow]=b4.w;
        __syncthreads();
#pragma unroll
        for (int kk = 0; kk < 16; kk++) {
            float4 ra = *(const float4*)&As[kk][tx*4];
            float4 rb = *(const float4*)&Bs[kk][ty*4];
            float av[4]={ra.x,ra.y,ra.z,ra.w}, bv[4]={rb.x,rb.y,rb.z,rb.w};
#pragma unroll
            for (int i=0;i<4;i++)
#pragma unroll
                for (int j=0;j<4;j++) acc[i][j] += av[i]*bv[j];
        }
        __syncthreads();
    }
    bool mb[4];
#pragma unroll
    for (int j=0;j<4;j++) mb[j] = g_mask[1+pair][b][s0+ty*4+j] != 0;
#pragma unroll
    for (int i=0;i<4;i++) {
        int t = t0 + tx*4 + i;
        bool ma = g_mask[0][b][t] != 0;
        float4 o;
        o.x = (ma&&mb[0]) ? acc[i][0] : -1e9f;
        o.y = (ma&&mb[1]) ? acc[i][1] : -1e9f;
        o.z = (ma&&mb[2]) ? acc[i][2] : -1e9f;
        o.w = (ma&&mb[3]) ? acc[i][3] : -1e9f;
        *(float4*)&g_S[pair][b][t][s0+ty*4] = o;
    }
}

__global__ void k_rowstats() {
    int t = blockIdx.x, b = blockIdx.y, pair = blockIdx.z, tid = threadIdx.x;
    const float* row = &g_S[pair][b][t][0];
    float v0=row[tid], v1=row[tid+128], v2=row[tid+256], v3=row[tid+384];
    float m = fmaxf(fmaxf(v0,v1), fmaxf(v2,v3));
    __shared__ float red[128];
    red[tid]=m; __syncthreads();
    for (int s=64;s>0;s>>=1){ if(tid<s) red[tid]=fmaxf(red[tid],red[tid+s]); __syncthreads(); }
    m = red[0]; __syncthreads();
    float sm_ = __expf(v0-m)+__expf(v1-m)+__expf(v2-m)+__expf(v3-m);
    red[tid]=sm_; __syncthreads();
    for (int s=64;s>0;s>>=1){ if(tid<s) red[tid]+=red[tid+s]; __syncthreads(); }
    if (tid==0){ g_rmax[pair][b][t]=m; g_rsum[pair][b][t]=red[0]; }
}

__global__ void k_colstats() {
    int s0 = blockIdx.x*32, b = blockIdx.y, pair = blockIdx.z, tid = threadIdx.x;
    int tx = tid&31, ty = tid>>5;
    float m = -3e38f, sum = 0.f;
    for (int t = ty; t < NT; t += 8) {
        float v = g_S[pair][b][t][s0+tx];
        float nm = fmaxf(m, v);
        sum = sum*__expf(m-nm) + __expf(v-nm);
        m = nm;
    }
    __shared__ float sm_[8][32], ss_[8][32];
    sm_[ty][tx]=m; ss_[ty][tx]=sum;
    __syncthreads();
    if (ty==0) {
        float M=sm_[0][tx], S=ss_[0][tx];
#pragma unroll
        for (int w=1;w<8;w++) {
            float m2=sm_[w][tx], s2=ss_[w][tx];
            float nm=fmaxf(M,m2);
            S = S*__expf(M-nm) + s2*__expf(m2-nm);
            M = nm;
        }
        g_cmax[pair][b][s0+tx]=M; g_csum[pair][b][s0+tx]=S;
    }
}

__global__ void __launch_bounds__(256) k_attnB() {
    int z = blockIdx.z, pair = z>>5, b = z&31;
    int t0 = blockIdx.x*64;
    __shared__ __align__(16) float As[16][68];
    __shared__ __align__(16) float Bs[16][132];
    __shared__ float rm[64], rs[64];
    int tid = threadIdx.x;
    if (tid < 64) {
        float m = g_rmax[pair][b][t0+tid];
        rm[tid] = m;
        rs[tid] = (m > -1e8f) ? 1.f/g_rsum[pair][b][t0+tid] : 0.f;
    }
    __syncthreads();
    int lrow=tid>>2, lq=tid&3;
    int srow=tid>>4, jq=tid&15;
    int tx=tid&15, ty=tid>>4;
    unsigned long long acc[4][4];
    float fz = 0.f;
#pragma unroll
    for (int i=0;i<4;i++)
#pragma unroll
        for (int j=0;j<4;j++)
            asm("mov.b64 %0,{%1,%1};" : "=l"(acc[i][j]) : "f"(fz));
    for (int k0 = 0; k0 < NT; k0 += 16) {
        float4 a4 = *(const float4*)&g_S[pair][b][t0+lrow][k0+lq*4];
        float m = rm[lrow];
        As[lq*4+0][lrow]=__expf(a4.x-m); As[lq*4+1][lrow]=__expf(a4.y-m);
        As[lq*4+2][lrow]=__expf(a4.z-m); As[lq*4+3][lrow]=__expf(a4.w-m);
        float4 b1 = *(const float4*)&g_feat[1+pair][b][k0+srow][jq*4];
        float4 b2 = *(const float4*)&g_feat[1+pair][b][k0+srow][64+jq*4];
        Bs[srow][jq*4+0]=b1.x; Bs[srow][jq*4+1]=b1.y; Bs[srow][jq*4+2]=b1.z; Bs[srow][jq*4+3]=b1.w;
        Bs[srow][64+jq*4+0]=b2.x; Bs[srow][64+jq*4+1]=b2.y; Bs[srow][64+jq*4+2]=b2.z; Bs[srow][64+jq*4+3]=b2.w;
        __syncthreads();
#pragma unroll
        for (int kk=0;kk<16;kk++) {
            float4 ra = *(const float4*)&As[kk][tx*4];
            ulonglong2 w1 = *(const ulonglong2*)&Bs[kk][ty*8];
            ulonglong2 w2 = *(const ulonglong2*)&Bs[kk][ty*8+4];
            float av[4] = {ra.x, ra.y, ra.z, ra.w};
#pragma unroll
            for (int i=0;i<4;i++) {
                unsigned long long h2;
                asm("mov.b64 %0,{%1,%1};" : "=l"(h2) : "f"(av[i]));
                asm("fma.rn.f32x2 %0,%1,%2,%0;" : "+l"(acc[i][0]) : "l"(h2), "l"(w1.x));
                asm("fma.rn.f32x2 %0,%1,%2,%0;" : "+l"(acc[i][1]) : "l"(h2), "l"(w1.y));
                asm("fma.rn.f32x2 %0,%1,%2,%0;" : "+l"(acc[i][2]) : "l"(h2), "l"(w2.x));
                asm("fma.rn.f32x2 %0,%1,%2,%0;" : "+l"(acc[i][3]) : "l"(h2), "l"(w2.y));
            }
        }
        __syncthreads();
    }
    int slot = g_slotOf[pair*64 + b];
#pragma unroll
    for (int i=0;i<4;i++) {
        int t = t0 + tx*4 + i;
        float sc = rs[tx*4+i];
        float v[8];
#pragma unroll
        for (int j = 0; j < 4; j++) {
            float lo, hi;
            asm("mov.b64 {%0,%1},%2;" : "=f"(lo), "=f"(hi) : "l"(acc[i][j]));
            v[j*2] = lo; v[j*2+1] = hi;
        }
        float4 f1 = *(const float4*)&g_feat[0][b][t][ty*8];
        float4 f2 = *(const float4*)&g_feat[0][b][t][ty*8+4];
        *(float4*)&g_X[slot][t][HF + ty*8] =
            make_float4(f1.x-v[0]*sc, f1.y-v[1]*sc, f1.z-v[2]*sc, f1.w-v[3]*sc);
        *(float4*)&g_X[slot][t][HF + ty*8+4] =
            make_float4(f2.x-v[4]*sc, f2.y-v[5]*sc, f2.z-v[6]*sc, f2.w-v[7]*sc);
    }
}

__global__ void __launch_bounds__(256) k_attnA() {
    int z = blockIdx.z, pair = z>>5, b = z&31;
    int s0 = blockIdx.x*64;
    __shared__ __align__(16) float As[16][68];
    __shared__ __align__(16) float Bs[16][132];
    __shared__ float cm[64], cs[64];
    int tid = threadIdx.x;
    if (tid < 64) {
        float m = g_cmax[pair][b][s0+tid];
        cm[tid] = m;
        cs[tid] = (m > -1e8f) ? 1.f/g_csum[pair][b][s0+tid] : 0.f;
    }
    __syncthreads();
    int r = tid>>4, q = tid&15;
    int tx = tid&15, ty = tid>>4;
    unsigned long long acc[4][4];
    float fz = 0.f;
#pragma unroll
    for (int i=0;i<4;i++)
#pragma unroll
        for (int j=0;j<4;j++)
            asm("mov.b64 %0,{%1,%1};" : "=l"(acc[i][j]) : "f"(fz));
    for (int k0 = 0; k0 < NT; k0 += 16) {
        float4 a4 = *(const float4*)&g_S[pair][b][k0+r][s0+q*4];
        As[r][q*4+0]=__expf(a4.x-cm[q*4+0]); As[r][q*4+1]=__expf(a4.y-cm[q*4+1]);
        As[r][q*4+2]=__expf(a4.z-cm[q*4+2]); As[r][q*4+3]=__expf(a4.w-cm[q*4+3]);
        float4 b1 = *(const float4*)&g_feat[0][b][k0+r][q*4];
        float4 b2 = *(const float4*)&g_feat[0][b][k0+r][64+q*4];
        Bs[r][q*4+0]=b1.x; Bs[r][q*4+1]=b1.y; Bs[r][q*4+2]=b1.z; Bs[r][q*4+3]=b1.w;
        Bs[r][64+q*4+0]=b2.x; Bs[r][64+q*4+1]=b2.y; Bs[r][64+q*4+2]=b2.z; Bs[r][64+q*4+3]=b2.w;
        __syncthreads();
#pragma unroll
        for (int kk=0;kk<16;kk++) {
            float4 ra = *(const float4*)&As[kk][tx*4];
            ulonglong2 w1 = *(const ulonglong2*)&Bs[kk][ty*8];
            ulonglong2 w2 = *(const ulonglong2*)&Bs[kk][ty*8+4];
            float av[4] = {ra.x, ra.y, ra.z, ra.w};
#pragma unroll
            for (int i=0;i<4;i++) {
                unsigned long long h2;
                asm("mov.b64 %0,{%1,%1};" : "=l"(h2) : "f"(av[i]));
                asm("fma.rn.f32x2 %0,%1,%2,%0;" : "+l"(acc[i][0]) : "l"(h2), "l"(w1.x));
                asm("fma.rn.f32x2 %0,%1,%2,%0;" : "+l"(acc[i][1]) : "l"(h2), "l"(w1.y));
                asm("fma.rn.f32x2 %0,%1,%2,%0;" : "+l"(acc[i][2]) : "l"(h2), "l"(w2.x));
                asm("fma.rn.f32x2 %0,%1,%2,%0;" : "+l"(acc[i][3]) : "l"(h2), "l"(w2.y));
            }
        }
        __syncthreads();
    }
    int slot = g_slotOf[pair*64 + 32 + b];
#pragma unroll
    for (int i=0;i<4;i++) {
        int s = s0 + tx*4 + i;
        float sc = cs[tx*4+i];
        float v[8];
#pragma unroll
        for (int j = 0; j < 4; j++) {
            float lo, hi;
            asm("mov.b64 {%0,%1},%2;" : "=f"(lo), "=f"(hi) : "l"(acc[i][j]));
            v[j*2] = lo; v[j*2+1] = hi;
        }
        float4 f1 = *(const float4*)&g_feat[1+pair][b][s][ty*8];
        float4 f2 = *(const float4*)&g_feat[1+pair][b][s][ty*8+4];
        *(float4*)&g_X[slot][s][HF + ty*8] =
            make_float4(f1.x-v[0]*sc, f1.y-v[1]*sc, f1.z-v[2]*sc, f1.w-v[3]*sc);
        *(float4*)&g_X[slot][s][HF + ty*8+4] =
            make_float4(f2.x-v[4]*sc, f2.y-v[5]*sc, f2.z-v[6]*sc, f2.w-v[7]*sc);
    }
}

__global__ void __launch_bounds__(256) k_ingate(const float* __restrict__ Wih,
                                                const float* __restrict__ bih,
                                                const float* __restrict__ bhh) {
    int t = blockIdx.x, n0 = blockIdx.y*128, s0 = blockIdx.z*64;
    int tid = threadIdx.x;
    if (t >= g_lens[s0+63]) {
        if (tid == 0)
            asm volatile("red.release.gpu.global.add.u32 [%0], 1;" :: "l"(&g_tdone[t]) : "memory");
        return;
    }
    __shared__ __align__(16) float As[16][68];
    __shared__ __align__(16) float Bs[16][132];
    int arow = tid>>2, aq = tid&3;
    int brow = tid>>1;
    int tx = tid&15, ty = tid>>4;
    unsigned long long acc[4][4];
    float fz = 0.f;
#pragma unroll
    for (int i=0;i<4;i++)
#pragma unroll
        for (int j=0;j<4;j++)
            asm("mov.b64 %0,{%1,%1};" : "=l"(acc[i][j]) : "f"(fz));

    for (int k0 = 0; k0 < NH; k0 += 16) {
        float4 a4 = *(const float4*)&g_X[s0+arow][t][k0 + aq*4];
        As[aq*4+0][arow]=a4.x; As[aq*4+1][arow]=a4.y; As[aq*4+2][arow]=a4.z; As[aq*4+3][arow]=a4.w;
#pragma unroll
        for (int p = 0; p < 2; p++) {
            int q = (tid&1)*2 + p;
            float4 b4 = *(const float4*)(Wih + (size_t)(n0+brow)*NH + k0 + q*4);
            Bs[q*4+0][brow]=b4.x; Bs[q*4+1][brow]=b4.y; Bs[q*4+2][brow]=b4.z; Bs[q*4+3][brow]=b4.w;
        }
        __syncthreads();
#pragma unroll
        for (int kk=0;kk<16;kk++) {
            float4 ra = *(const float4*)&As[kk][tx*4];
            ulonglong2 w1 = *(const ulonglong2*)&Bs[kk][ty*8];
            ulonglong2 w2 = *(const ulonglong2*)&Bs[kk][ty*8+4];
            float av[4] = {ra.x, ra.y, ra.z, ra.w};
#pragma unroll
            for (int i=0;i<4;i++) {
                unsigned long long h2;
                asm("mov.b64 %0,{%1,%1};" : "=l"(h2) : "f"(av[i]));
                asm("fma.rn.f32x2 %0,%1,%2,%0;" : "+l"(acc[i][0]) : "l"(h2), "l"(w1.x));
                asm("fma.rn.f32x2 %0,%1,%2,%0;" : "+l"(acc[i][1]) : "l"(h2), "l"(w1.y));
                asm("fma.rn.f32x2 %0,%1,%2,%0;" : "+l"(acc[i][2]) : "l"(h2), "l"(w2.x));
                asm("fma.rn.f32x2 %0,%1,%2,%0;" : "+l"(acc[i][3]) : "l"(h2), "l"(w2.y));
            }
        }
        __syncthreads();
    }
#pragma unroll
    for (int j = 0; j < 8; j++) {
        int n = n0 + ty*8 + j;
        float bs = bih[n] + bhh[n];
        float v[4];
#pragma unroll
        for (int i = 0; i < 4; i++) {
            float lo, hi;
            asm("mov.b64 {%0,%1},%2;" : "=f"(lo), "=f"(hi) : "l"(acc[i][j>>1]));
            v[i] = ((j & 1) ? hi : lo) + bs;
        }
        *(float4*)&g_G[t][n][s0 + tx*4] = make_float4(v[0], v[1], v[2], v[3]);
    }
    __syncthreads();
    if (tid == 0)
        asm volatile("red.release.gpu.global.add.u32 [%0], 1;" :: "l"(&g_tdone[t]) : "memory");
}

// acquire/release barrier (proven): red.release arrival, ld.acquire spin
__device__ __forceinline__ void gridbar8(int sg, unsigned int target) {
    __syncthreads();
    if (threadIdx.x == 0) {
        unsigned int* cp = &g_cnt8[sg][0];
        asm volatile("red.release.gpu.global.add.u32 [%0], 1;" :: "l"(cp) : "memory");
        unsigned int v;
        while (true) {
            asm volatile("ld.acquire.gpu.global.u32 %0, [%1];" : "=r"(v) : "l"(cp) : "memory");
            if (v >= target) break;
            __nanosleep(64);
        }
    }
    __syncthreads();
}

// wait until all 16 ingate CTAs for time t have committed G[t]
__device__ __forceinline__ void wait_t(int t) {
    if ((threadIdx.x & 31) == 0) {
        const unsigned int* p = &g_tdone[t];
        unsigned int v;
        while (true) {
            asm volatile("ld.acquire.gpu.global.u32 %0, [%1];" : "=r"(v) : "l"(p) : "memory");
            if (v >= 16u) break;
            __nanosleep(128);
        }
    }
    __syncwarp();
}

// 128 CTAs: 16 unit-groups (16 units each) x 8 slot-groups (16 slots each).
#define REC_SMEM ((16384 + 4096) * 4 + 1024)

__global__ void __launch_bounds__(256, 1) k_rec(const float* __restrict__ Whh) {
    extern __shared__ float sh[];
    float* w_s = sh;           // [k(256)][uu(16)][gate(4)]  64 KB
    float* h_s = sh + 16384;   // [k(256)][sl(16)]           16 KB
    int tid = threadIdx.x;
    int ug = blockIdx.x >> 3;
    int sg = blockIdx.x & 7;
    int u0 = ug * 16, s0 = sg * 16;

    for (int i = tid; i < 16384; i += 256) {
        int k = i >> 6, r = i & 63, uu = r >> 2, g = r & 3;
        w_s[i] = Whh[(size_t)((g << 8) + u0 + uu)*256 + k];
    }

    int w = tid >> 5, lane = tid & 31;
    int uu = (w << 1) + (lane >> 4);
    int sl = lane & 15;
    int u = u0 + uu, slot = s0 + sl;
    int mylen = g_lens[slot];
    int glen = g_lens[s0 + 15];
    float c = 0.f;
    g_H[0][u][slot] = 0.f;
    unsigned int ep = 1;
    gridbar8(sg, ep << 4);

    wait_t(0);
    const float* gbase = &g_G[0][u][slot];
    float gi = __ldcg(gbase + 0);
    float gf = __ldcg(gbase + 256*128);
    float gg = __ldcg(gbase + 512*128);
    float go = __ldcg(gbase + 768*128);

    for (int t = 0; t < glen; t++) {
        int buf = t & 1;
#pragma unroll
        for (int p = 0; p < 4; p++) {
            int idx = tid + (p << 8);
            int k = idx >> 2, f4 = idx & 3;
            float4 v = __ldcg((const float4*)&g_H[buf][k][s0 + f4*4]);
            *(float4*)&h_s[(k << 4) + (f4 << 2)] = v;
        }
        __syncthreads();
        unsigned long long aif, ago, h2;
        asm("mov.b64 %0,{%1,%2};" : "=l"(aif) : "f"(gi), "f"(gf));
        asm("mov.b64 %0,{%1,%2};" : "=l"(ago) : "f"(gg), "f"(go));
        const float* wp = w_s + uu*4;
        const float* hp = h_s + sl;
#pragma unroll 8
        for (int k = 0; k < 256; k++) {
            float hv = hp[k << 4];
            ulonglong2 w2 = *(const ulonglong2*)(wp + (k << 6));
            asm("mov.b64 %0,{%1,%1};" : "=l"(h2) : "f"(hv));
            asm("fma.rn.f32x2 %0,%1,%2,%0;" : "+l"(aif) : "l"(h2), "l"(w2.x));
            asm("fma.rn.f32x2 %0,%1,%2,%0;" : "+l"(ago) : "l"(h2), "l"(w2.y));
        }
        float ri, rf, rg, ro;
        asm("mov.b64 {%0,%1},%2;" : "=f"(ri), "=f"(rf) : "l"(aif));
        asm("mov.b64 {%0,%1},%2;" : "=f"(rg), "=f"(ro) : "l"(ago));
        float iv = fsig(ri);
        float fv = fsig(rf);
        float gv = ftanh(rg);
        float ov = fsig(ro);
        c = fv*c + iv*gv;
        float hval = ov*ftanh(c);
        g_H[1-buf][u][slot] = hval;
        if (t + 1 == mylen) g_Hsel[u][slot] = hval;
        int tn = (t + 1 < glen) ? (t + 1) : t;
        wait_t(tn);
        const float* gp = &g_G[tn][u][slot];
        gi = __ldcg(gp + 0);
        gf = __ldcg(gp + 256*128);
        gg = __ldcg(gp + 512*128);
        go = __ldcg(gp + 768*128);
        ep++;
        gridbar8(sg, ep << 4);
    }
}

__global__ void k_final(const float* W1, const float* b1, const float* W2, const float* b2,
                        const float* W3, const float* b3, float* out) {
    int b = blockIdx.x, pair = blockIdx.y, j = threadIdx.x;
    __shared__ float oa[NH], ob[NH], red[NH];
    int sa = g_slotOf[pair*64 + b], sb = g_slotOf[pair*64 + 32 + b];
    oa[j] = g_Hsel[j][sa]; ob[j] = g_Hsel[j][sb];
    __syncthreads();
    float u1 = b1[j], u2 = b2[j], u3 = b3[j];
    for (int k = 0; k < NH; k++) {
        float o = oa[k];
        u1 += o*W1[(size_t)j*NH+k];
        u2 += o*W2[(size_t)j*NH+k];
        u3 += o*W3[(size_t)j*NH+k];
    }
    float s1 = fsig(u1);
    float l2 = u2 >= 0.f ? u2 : 0.1f*u2;
    float cg = s1*l2;
    float s3 = fsig(u3);
    float lc = cg >= 0.f ? cg : 0.1f*cg;
    float fa = oa[j] + s3*lc;
    float d = fa - ob[j] + 1e-6f;
    red[j] = d*d;
    __syncthreads();
    for (int s = 128; s > 0; s >>= 1) { if (j < s) red[j] += red[j+s]; __syncthreads(); }
    if (j == 0) out[pair*32 + b] = expf(sqrtf(red[0]));
}

extern "C" void kernel_launch(void* const* d_in, const int* in_sizes, int n_in,
                              void* d_out, int out_size) {
    const float* anchor = (const float*)d_in[0];
    const float* trajs  = (const float*)d_in[1];
    const float* neg    = (const float*)d_in[2];
    const int* la = (const int*)d_in[3];
    const int* lt = (const int*)d_in[4];
    const int* ln = (const int*)d_in[5];
    const float* Wm  = (const float*)d_in[6];
    const float* bm  = (const float*)d_in[7];
    const float* Wih = (const float*)d_in[8];
    const float* Whh = (const float*)d_in[9];
    const float* bih = (const float*)d_in[10];
    const float* bhh = (const float*)d_in[11];
    const float* W1 = (const float*)d_in[12];
    const float* b1 = (const float*)d_in[13];
    const float* W2 = (const float*)d_in[14];
    const float* b2 = (const float*)d_in[15];
    const float* W3 = (const float*)d_in[16];
    const float* b3 = (const float*)d_in[17];
    float* out = (float*)d_out;

    static int init_done = 0;
    static cudaStream_t s2;
    static cudaEvent_t e1, e2;
    if (!init_done) {
        cudaFuncSetAttribute(k_rec, cudaFuncAttributeMaxDynamicSharedMemorySize, REC_SMEM);
        cudaStreamCreateWithFlags(&s2, cudaStreamNonBlocking);
        cudaEventCreateWithFlags(&e1, cudaEventDisableTiming);
        cudaEventCreateWithFlags(&e2, cudaEventDisableTiming);
        init_done = 1;
    }

    k_prep<<<1, 128>>>(la, lt, ln);
    k_feat<<<dim3(NT, NB, 3), 128>>>(anchor, trajs, neg, Wm, bm);
    k_scores<<<dim3(8, 8, 64), 256>>>();
    k_rowstats<<<dim3(NT, NB, 2), 128>>>();
    k_colstats<<<dim3(16, NB, 2), 256>>>();
    k_attnB<<<dim3(8, 1, 64), 256>>>();
    k_attnA<<<dim3(8, 1, 64), 256>>>();
    // fork: rec (s2) runs concurrently with ingate (main), gated by g_tdone flags
    cudaEventRecord(e1, 0);
    cudaStreamWaitEvent(s2, e1, 0);
    k_ingate<<<dim3(NT, 8, 2), 256>>>(Wih, bih, bhh);
    k_rec<<<128, 256, REC_SMEM, s2>>>(Whh);
    cudaEventRecord(e2, s2);
    cudaStreamWaitEvent(0, e2, 0);
    k_final<<<dim3(NB, 2), 256>>>(W1, b1, W2, b2, W3, b3, out);
}

// round 16
// speedup vs baseline: 1.3142x; 1.3142x over previous
#include <cuda_runtime.h>
#include <math.h>

#define NT 512
#define NB 32
#define HF 128
#define NH 256

__device__ __align__(16) float g_feat[3][NB][NT][HF];
__device__ unsigned char g_mask[3][NB][NT];
__device__ __align__(16) float g_S[2][NB][NT][NT];
__device__ float g_rmax[2][NB][NT], g_rsum[2][NB][NT];
__device__ float g_cmax[2][NB][NT], g_csum[2][NB][NT];
__device__ __align__(16) float g_X[128][NT][NH];
__device__ __align__(16) float g_G[NT][1024][128];
__device__ __align__(16) float g_H[2][NH][128];
__device__ __align__(16) float g_Hsel[NH][128];
__device__ int g_lens[128], g_map[128], g_slotOf[128];
__device__ __align__(128) unsigned int g_cnt8[8][32];

__device__ __forceinline__ float fsig(float x) { return 1.f / (1.f + __expf(-x)); }
__device__ __forceinline__ float ftanh(float x) { return 2.f / (1.f + __expf(-2.f * x)) - 1.f; }

__global__ void k_prep(const int* la, const int* lt, const int* ln) {
    __shared__ int sl[128], si[128];
    int i = threadIdx.x, l = i >> 5, b = i & 31;
    int len = (l == 1) ? lt[b] : (l == 3) ? ln[b] : la[b];
    sl[i] = len; si[i] = i;
    __syncthreads();
    if (i == 0) {
        for (int a = 1; a < 128; a++) {
            int lv = sl[a], iv = si[a], c = a - 1;
            while (c >= 0 && sl[c] > lv) { sl[c+1]=sl[c]; si[c+1]=si[c]; c--; }
            sl[c+1]=lv; si[c+1]=iv;
        }
        for (int q = 0; q < 8; q++) g_cnt8[q][0] = 0u;
    }
    __syncthreads();
    g_lens[i] = sl[i]; g_map[i] = si[i]; g_slotOf[si[i]] = i;
}

__global__ void k_feat(const float* A, const float* T_, const float* N_,
                       const float* Wm, const float* bm) {
    int t = blockIdx.x, b = blockIdx.y, tr = blockIdx.z, j = threadIdx.x;
    const float* base = tr==0 ? A : (tr==1 ? T_ : N_);
    const float* x = base + ((size_t)b*NT + t)*4;
    float v = x[0]*Wm[2*j] + x[1]*Wm[2*j+1] + bm[j];
    float fv = v >= 0.f ? v : 0.1f*v;
    g_feat[tr][b][t][j] = fv;
    if (tr == 0) {
        g_X[g_slotOf[b]][t][j] = fv;
        g_X[g_slotOf[64 + b]][t][j] = fv;
    } else if (tr == 1) {
        g_X[g_slotOf[32 + b]][t][j] = fv;
    } else {
        g_X[g_slotOf[96 + b]][t][j] = fv;
    }
    if (j == 0) g_mask[tr][b][t] = (x[3]*128.f + x[2] - 257.f) > 0.5f ? 1 : 0;
}

__global__ void k_scores() {
    int z = blockIdx.z, pair = z >> 5, b = z & 31;
    int t0 = blockIdx.x*64, s0 = blockIdx.y*64;
    __shared__ __align__(16) float As[16][68], Bs[16][68];
    int tid = threadIdx.x, lrow = tid>>2, lq = tid&3, tx = tid&15, ty = tid>>4;
    float acc[4][4] = {};
    const float* A = &g_feat[0][b][0][0];
    const float* Bf = &g_feat[1+pair][b][0][0];
    for (int k0 = 0; k0 < HF; k0 += 16) {
        float4 a4 = *(const float4*)(A + (size_t)(t0+lrow)*HF + k0 + lq*4);
        float4 b4 = *(const float4*)(Bf + (size_t)(s0+lrow)*HF + k0 + lq*4);
        As[lq*4+0][lrow]=a4.x; As[lq*4+1][lrow]=a4.y; As[lq*4+2][lrow]=a4.z; As[lq*4+3][lrow]=a4.w;
        Bs[lq*4+0][lrow]=b4.x; Bs[lq*4+1][lrow]=b4.y; Bs[lq*4+2][lrow]=b4.z; Bs[lq*4+3][lrow]=b4.w;
        __syncthreads();
#pragma unroll
        for (int kk = 0; kk < 16; kk++) {
            float4 ra = *(const float4*)&As[kk][tx*4];
            float4 rb = *(const float4*)&Bs[kk][ty*4];
            float av[4]={ra.x,ra.y,ra.z,ra.w}, bv[4]={rb.x,rb.y,rb.z,rb.w};
#pragma unroll
            for (int i=0;i<4;i++)
#pragma unroll
                for (int j=0;j<4;j++) acc[i][j] += av[i]*bv[j];
        }
        __syncthreads();
    }
    bool mb[4];
#pragma unroll
    for (int j=0;j<4;j++) mb[j] = g_mask[1+pair][b][s0+ty*4+j] != 0;
#pragma unroll
    for (int i=0;i<4;i++) {
        int t = t0 + tx*4 + i;
        bool ma = g_mask[0][b][t] != 0;
        float4 o;
        o.x = (ma&&mb[0]) ? acc[i][0] : -1e9f;
        o.y = (ma&&mb[1]) ? acc[i][1] : -1e9f;
        o.z = (ma&&mb[2]) ? acc[i][2] : -1e9f;
        o.w = (ma&&mb[3]) ? acc[i][3] : -1e9f;
        *(float4*)&g_S[pair][b][t][s0+ty*4] = o;
    }
}

__global__ void k_rowstats() {
    int t = blockIdx.x, b = blockIdx.y, pair = blockIdx.z, tid = threadIdx.x;
    const float* row = &g_S[pair][b][t][0];
    float v0=row[tid], v1=row[tid+128], v2=row[tid+256], v3=row[tid+384];
    float m = fmaxf(fmaxf(v0,v1), fmaxf(v2,v3));
    __shared__ float red[128];
    red[tid]=m; __syncthreads();
    for (int s=64;s>0;s>>=1){ if(tid<s) red[tid]=fmaxf(red[tid],red[tid+s]); __syncthreads(); }
    m = red[0]; __syncthreads();
    float sm_ = __expf(v0-m)+__expf(v1-m)+__expf(v2-m)+__expf(v3-m);
    red[tid]=sm_; __syncthreads();
    for (int s=64;s>0;s>>=1){ if(tid<s) red[tid]+=red[tid+s]; __syncthreads(); }
    if (tid==0){ g_rmax[pair][b][t]=m; g_rsum[pair][b][t]=red[0]; }
}

__global__ void k_colstats() {
    int s0 = blockIdx.x*32, b = blockIdx.y, pair = blockIdx.z, tid = threadIdx.x;
    int tx = tid&31, ty = tid>>5;
    float m = -3e38f, sum = 0.f;
    for (int t = ty; t < NT; t += 8) {
        float v = g_S[pair][b][t][s0+tx];
        float nm = fmaxf(m, v);
        sum = sum*__expf(m-nm) + __expf(v-nm);
        m = nm;
    }
    __shared__ float sm_[8][32], ss_[8][32];
    sm_[ty][tx]=m; ss_[ty][tx]=sum;
    __syncthreads();
    if (ty==0) {
        float M=sm_[0][tx], S=ss_[0][tx];
#pragma unroll
        for (int w=1;w<8;w++) {
            float m2=sm_[w][tx], s2=ss_[w][tx];
            float nm=fmaxf(M,m2);
            S = S*__expf(M-nm) + s2*__expf(m2-nm);
            M = nm;
        }
        g_cmax[pair][b][s0+tx]=M; g_csum[pair][b][s0+tx]=S;
    }
}

__global__ void __launch_bounds__(256) k_attnB() {
    int z = blockIdx.z, pair = z>>5, b = z&31;
    int t0 = blockIdx.x*64;
    __shared__ __align__(16) float As[16][68];
    __shared__ __align__(16) float Bs[16][132];
    __shared__ float rm[64], rs[64];
    int tid = threadIdx.x;
    if (tid < 64) {
        float m = g_rmax[pair][b][t0+tid];
        rm[tid] = m;
        rs[tid] = (m > -1e8f) ? 1.f/g_rsum[pair][b][t0+tid] : 0.f;
    }
    __syncthreads();
    int lrow=tid>>2, lq=tid&3;
    int srow=tid>>4, jq=tid&15;
    int tx=tid&15, ty=tid>>4;
    unsigned long long acc[4][4];
    float fz = 0.f;
#pragma unroll
    for (int i=0;i<4;i++)
#pragma unroll
        for (int j=0;j<4;j++)
            asm("mov.b64 %0,{%1,%1};" : "=l"(acc[i][j]) : "f"(fz));
    for (int k0 = 0; k0 < NT; k0 += 16) {
        float4 a4 = *(const float4*)&g_S[pair][b][t0+lrow][k0+lq*4];
        float m = rm[lrow];
        As[lq*4+0][lrow]=__expf(a4.x-m); As[lq*4+1][lrow]=__expf(a4.y-m);
        As[lq*4+2][lrow]=__expf(a4.z-m); As[lq*4+3][lrow]=__expf(a4.w-m);
        float4 b1 = *(const float4*)&g_feat[1+pair][b][k0+srow][jq*4];
        float4 b2 = *(const float4*)&g_feat[1+pair][b][k0+srow][64+jq*4];
        Bs[srow][jq*4+0]=b1.x; Bs[srow][jq*4+1]=b1.y; Bs[srow][jq*4+2]=b1.z; Bs[srow][jq*4+3]=b1.w;
        Bs[srow][64+jq*4+0]=b2.x; Bs[srow][64+jq*4+1]=b2.y; Bs[srow][64+jq*4+2]=b2.z; Bs[srow][64+jq*4+3]=b2.w;
        __syncthreads();
#pragma unroll
        for (int kk=0;kk<16;kk++) {
            float4 ra = *(const float4*)&As[kk][tx*4];
            ulonglong2 w1 = *(const ulonglong2*)&Bs[kk][ty*8];
            ulonglong2 w2 = *(const ulonglong2*)&Bs[kk][ty*8+4];
            float av[4] = {ra.x, ra.y, ra.z, ra.w};
#pragma unroll
            for (int i=0;i<4;i++) {
                unsigned long long h2;
                asm("mov.b64 %0,{%1,%1};" : "=l"(h2) : "f"(av[i]));
                asm("fma.rn.f32x2 %0,%1,%2,%0;" : "+l"(acc[i][0]) : "l"(h2), "l"(w1.x));
                asm("fma.rn.f32x2 %0,%1,%2,%0;" : "+l"(acc[i][1]) : "l"(h2), "l"(w1.y));
                asm("fma.rn.f32x2 %0,%1,%2,%0;" : "+l"(acc[i][2]) : "l"(h2), "l"(w2.x));
                asm("fma.rn.f32x2 %0,%1,%2,%0;" : "+l"(acc[i][3]) : "l"(h2), "l"(w2.y));
            }
        }
        __syncthreads();
    }
    int slot = g_slotOf[pair*64 + b];
#pragma unroll
    for (int i=0;i<4;i++) {
        int t = t0 + tx*4 + i;
        float sc = rs[tx*4+i];
        float v[8];
#pragma unroll
        for (int j = 0; j < 4; j++) {
            float lo, hi;
            asm("mov.b64 {%0,%1},%2;" : "=f"(lo), "=f"(hi) : "l"(acc[i][j]));
            v[j*2] = lo; v[j*2+1] = hi;
        }
        float4 f1 = *(const float4*)&g_feat[0][b][t][ty*8];
        float4 f2 = *(const float4*)&g_feat[0][b][t][ty*8+4];
        *(float4*)&g_X[slot][t][HF + ty*8] =
            make_float4(f1.x-v[0]*sc, f1.y-v[1]*sc, f1.z-v[2]*sc, f1.w-v[3]*sc);
        *(float4*)&g_X[slot][t][HF + ty*8+4] =
            make_float4(f2.x-v[4]*sc, f2.y-v[5]*sc, f2.z-v[6]*sc, f2.w-v[7]*sc);
    }
}

__global__ void __launch_bounds__(256) k_attnA() {
    int z = blockIdx.z, pair = z>>5, b = z&31;
    int s0 = blockIdx.x*64;
    __shared__ __align__(16) float As[16][68];
    __shared__ __align__(16) float Bs[16][132];
    __shared__ float cm[64], cs[64];
    int tid = threadIdx.x;
    if (tid < 64) {
        float m = g_cmax[pair][b][s0+tid];
        cm[tid] = m;
        cs[tid] = (m > -1e8f) ? 1.f/g_csum[pair][b][s0+tid] : 0.f;
    }
    __syncthreads();
    int r = tid>>4, q = tid&15;
    int tx = tid&15, ty = tid>>4;
    unsigned long long acc[4][4];
    float fz = 0.f;
#pragma unroll
    for (int i=0;i<4;i++)
#pragma unroll
        for (int j=0;j<4;j++)
            asm("mov.b64 %0,{%1,%1};" : "=l"(acc[i][j]) : "f"(fz));
    for (int k0 = 0; k0 < NT; k0 += 16) {
        float4 a4 = *(const float4*)&g_S[pair][b][k0+r][s0+q*4];
        As[r][q*4+0]=__expf(a4.x-cm[q*4+0]); As[r][q*4+1]=__expf(a4.y-cm[q*4+1]);
        As[r][q*4+2]=__expf(a4.z-cm[q*4+2]); As[r][q*4+3]=__expf(a4.w-cm[q*4+3]);
        float4 b1 = *(const float4*)&g_feat[0][b][k0+r][q*4];
        float4 b2 = *(const float4*)&g_feat[0][b][k0+r][64+q*4];
        Bs[r][q*4+0]=b1.x; Bs[r][q*4+1]=b1.y; Bs[r][q*4+2]=b1.z; Bs[r][q*4+3]=b1.w;
        Bs[r][64+q*4+0]=b2.x; Bs[r][64+q*4+1]=b2.y; Bs[r][64+q*4+2]=b2.z; Bs[r][64+q*4+3]=b2.w;
        __syncthreads();
#pragma unroll
        for (int kk=0;kk<16;kk++) {
            float4 ra = *(const float4*)&As[kk][tx*4];
            ulonglong2 w1 = *(const ulonglong2*)&Bs[kk][ty*8];
            ulonglong2 w2 = *(const ulonglong2*)&Bs[kk][ty*8+4];
            float av[4] = {ra.x, ra.y, ra.z, ra.w};
#pragma unroll
            for (int i=0;i<4;i++) {
                unsigned long long h2;
                asm("mov.b64 %0,{%1,%1};" : "=l"(h2) : "f"(av[i]));
                asm("fma.rn.f32x2 %0,%1,%2,%0;" : "+l"(acc[i][0]) : "l"(h2), "l"(w1.x));
                asm("fma.rn.f32x2 %0,%1,%2,%0;" : "+l"(acc[i][1]) : "l"(h2), "l"(w1.y));
                asm("fma.rn.f32x2 %0,%1,%2,%0;" : "+l"(acc[i][2]) : "l"(h2), "l"(w2.x));
                asm("fma.rn.f32x2 %0,%1,%2,%0;" : "+l"(acc[i][3]) : "l"(h2), "l"(w2.y));
            }
        }
        __syncthreads();
    }
    int slot = g_slotOf[pair*64 + 32 + b];
#pragma unroll
    for (int i=0;i<4;i++) {
        int s = s0 + tx*4 + i;
        float sc = cs[tx*4+i];
        float v[8];
#pragma unroll
        for (int j = 0; j < 4; j++) {
            float lo, hi;
            asm("mov.b64 {%0,%1},%2;" : "=f"(lo), "=f"(hi) : "l"(acc[i][j]));
            v[j*2] = lo; v[j*2+1] = hi;
        }
        float4 f1 = *(const float4*)&g_feat[1+pair][b][s][ty*8];
        float4 f2 = *(const float4*)&g_feat[1+pair][b][s][ty*8+4];
        *(float4*)&g_X[slot][s][HF + ty*8] =
            make_float4(f1.x-v[0]*sc, f1.y-v[1]*sc, f1.z-v[2]*sc, f1.w-v[3]*sc);
        *(float4*)&g_X[slot][s][HF + ty*8+4] =
            make_float4(f2.x-v[4]*sc, f2.y-v[5]*sc, f2.z-v[6]*sc, f2.w-v[7]*sc);
    }
}

__global__ void __launch_bounds__(256) k_ingate(const float* __restrict__ Wih,
                                                const float* __restrict__ bih,
                                                const float* __restrict__ bhh) {
    int t = blockIdx.x, n0 = blockIdx.y*128, s0 = blockIdx.z*64;
    if (t >= g_lens[s0+63]) return;
    __shared__ __align__(16) float As[16][68];
    __shared__ __align__(16) float Bs[16][132];
    int tid = threadIdx.x;
    int arow = tid>>2, aq = tid&3;
    int brow = tid>>1;
    int tx = tid&15, ty = tid>>4;
    unsigned long long acc[4][4];
    float fz = 0.f;
#pragma unroll
    for (int i=0;i<4;i++)
#pragma unroll
        for (int j=0;j<4;j++)
            asm("mov.b64 %0,{%1,%1};" : "=l"(acc[i][j]) : "f"(fz));

    for (int k0 = 0; k0 < NH; k0 += 16) {
        float4 a4 = *(const float4*)&g_X[s0+arow][t][k0 + aq*4];
        As[aq*4+0][arow]=a4.x; As[aq*4+1][arow]=a4.y; As[aq*4+2][arow]=a4.z; As[aq*4+3][arow]=a4.w;
#pragma unroll
        for (int p = 0; p < 2; p++) {
            int q = (tid&1)*2 + p;
            float4 b4 = *(const float4*)(Wih + (size_t)(n0+brow)*NH + k0 + q*4);
            Bs[q*4+0][brow]=b4.x; Bs[q*4+1][brow]=b4.y; Bs[q*4+2][brow]=b4.z; Bs[q*4+3][brow]=b4.w;
        }
        __syncthreads();
#pragma unroll
        for (int kk=0;kk<16;kk++) {
            float4 ra = *(const float4*)&As[kk][tx*4];
            ulonglong2 w1 = *(const ulonglong2*)&Bs[kk][ty*8];
            ulonglong2 w2 = *(const ulonglong2*)&Bs[kk][ty*8+4];
            float av[4] = {ra.x, ra.y, ra.z, ra.w};
#pragma unroll
            for (int i=0;i<4;i++) {
                unsigned long long h2;
                asm("mov.b64 %0,{%1,%1};" : "=l"(h2) : "f"(av[i]));
                asm("fma.rn.f32x2 %0,%1,%2,%0;" : "+l"(acc[i][0]) : "l"(h2), "l"(w1.x));
                asm("fma.rn.f32x2 %0,%1,%2,%0;" : "+l"(acc[i][1]) : "l"(h2), "l"(w1.y));
                asm("fma.rn.f32x2 %0,%1,%2,%0;" : "+l"(acc[i][2]) : "l"(h2), "l"(w2.x));
                asm("fma.rn.f32x2 %0,%1,%2,%0;" : "+l"(acc[i][3]) : "l"(h2), "l"(w2.y));
            }
        }
        __syncthreads();
    }
#pragma unroll
    for (int j = 0; j < 8; j++) {
        int n = n0 + ty*8 + j;
        float bs = bih[n] + bhh[n];
        float v[4];
#pragma unroll
        for (int i = 0; i < 4; i++) {
            float lo, hi;
            asm("mov.b64 {%0,%1},%2;" : "=f"(lo), "=f"(hi) : "l"(acc[i][j>>1]));
            v[i] = ((j & 1) ? hi : lo) + bs;
        }
        *(float4*)&g_G[t][n][s0 + tx*4] = make_float4(v[0], v[1], v[2], v[3]);
    }
}

// acquire/release barrier (proven): red.release arrival, ld.acquire spin
__device__ __forceinline__ void gridbar8(int sg, unsigned int target) {
    __syncthreads();
    if (threadIdx.x == 0) {
        unsigned int* cp = &g_cnt8[sg][0];
        asm volatile("red.release.gpu.global.add.u32 [%0], 1;" :: "l"(cp) : "memory");
        unsigned int v;
        while (true) {
            asm volatile("ld.acquire.gpu.global.u32 %0, [%1];" : "=r"(v) : "l"(cp) : "memory");
            if (v >= target) break;
            __nanosleep(64);
        }
    }
    __syncthreads();
}

// 128 CTAs: 16 unit-groups x 8 slot-groups.
// NEW layouts: w_s[kq][uu][gate][q] (64KB), h_s[kq][sl][q] (16KB).
// Warp covers 4 uu x 8 sl -> h-LDS128 = 128B distinct, w-LDS128 = 64B distinct.
#define REC_SMEM ((16384 + 4096) * 4 + 1024)

__global__ void __launch_bounds__(256, 1) k_rec(const float* __restrict__ Whh) {
    extern __shared__ float sh[];
    float* w_s = sh;           // [kq(64)][uu(16)][g(4)][q(4)]  64 KB
    float* h_s = sh + 16384;   // [kq(64)][sl(16)][q(4)]        16 KB
    int tid = threadIdx.x;
    int ug = blockIdx.x >> 3;
    int sg = blockIdx.x & 7;
    int u0 = ug * 16, s0 = sg * 16;

    // load Whh slice into [kq][uu][g][q]
    for (int i = tid; i < 16384; i += 256) {
        int kq = i >> 8, rem = i & 255;
        int uu = rem >> 4, g = (rem >> 2) & 3, q = rem & 3;
        w_s[i] = Whh[(size_t)((g << 8) + u0 + uu)*256 + (kq << 2) + q];
    }

    int w = tid >> 5, lane = tid & 31;
    int sl = ((w & 1) << 3) + (lane & 7);      // 0..15
    int uu = ((w >> 1) << 2) + (lane >> 3);    // 0..15
    int u = u0 + uu, slot = s0 + sl;
    int mylen = g_lens[slot];
    int glen = g_lens[s0 + 15];
    float c = 0.f;
    g_H[0][u][slot] = 0.f;
    unsigned int ep = 1;
    gridbar8(sg, ep << 4);

    const float* gbase = &g_G[0][u][slot];
    float gi = __ldcg(gbase + 0);
    float gf = __ldcg(gbase + 256*128);
    float gg = __ldcg(gbase + 512*128);
    float go = __ldcg(gbase + 768*128);

    for (int t = 0; t < glen; t++) {
        int buf = t & 1;
        // stage h tile into [kq][sl][q]: 1024 float4 reads, scalar smem scatter
#pragma unroll
        for (int p = 0; p < 4; p++) {
            int idx = tid + (p << 8);
            int k = idx >> 2, f4 = idx & 3;
            float4 v = __ldcg((const float4*)&g_H[buf][k][s0 + f4*4]);
            int kq = k >> 2, q = k & 3;
            int base = (kq << 6) + ((f4 << 2) << 2) + q;   // kq*64 + (f4*4)*4 + q
            h_s[base +  0] = v.x;
            h_s[base +  4] = v.y;
            h_s[base +  8] = v.z;
            h_s[base + 12] = v.w;
        }
        __syncthreads();
        unsigned long long a0, a1, a2, a3;
        float fz = 0.f;
        asm("mov.b64 %0,{%1,%1};" : "=l"(a0) : "f"(fz));
        asm("mov.b64 %0,{%1,%1};" : "=l"(a1) : "f"(fz));
        asm("mov.b64 %0,{%1,%1};" : "=l"(a2) : "f"(fz));
        asm("mov.b64 %0,{%1,%1};" : "=l"(a3) : "f"(fz));
        const float* hp = h_s + (sl << 2);
        const float* wp = w_s + (uu << 4);
#pragma unroll 8
        for (int kq = 0; kq < 64; kq++) {
            ulonglong2 hh = *(const ulonglong2*)(hp + (kq << 6));
            ulonglong2 w0 = *(const ulonglong2*)(wp + (kq << 8));
            ulonglong2 w1 = *(const ulonglong2*)(wp + (kq << 8) + 4);
            ulonglong2 w2 = *(const ulonglong2*)(wp + (kq << 8) + 8);
            ulonglong2 w3 = *(const ulonglong2*)(wp + (kq << 8) + 12);
            asm("fma.rn.f32x2 %0,%1,%2,%0;" : "+l"(a0) : "l"(hh.x), "l"(w0.x));
            asm("fma.rn.f32x2 %0,%1,%2,%0;" : "+l"(a1) : "l"(hh.x), "l"(w1.x));
            asm("fma.rn.f32x2 %0,%1,%2,%0;" : "+l"(a2) : "l"(hh.x), "l"(w2.x));
            asm("fma.rn.f32x2 %0,%1,%2,%0;" : "+l"(a3) : "l"(hh.x), "l"(w3.x));
            asm("fma.rn.f32x2 %0,%1,%2,%0;" : "+l"(a0) : "l"(hh.y), "l"(w0.y));
            asm("fma.rn.f32x2 %0,%1,%2,%0;" : "+l"(a1) : "l"(hh.y), "l"(w1.y));
            asm("fma.rn.f32x2 %0,%1,%2,%0;" : "+l"(a2) : "l"(hh.y), "l"(w2.y));
            asm("fma.rn.f32x2 %0,%1,%2,%0;" : "+l"(a3) : "l"(hh.y), "l"(w3.y));
        }
        float lo, hi, ri, rf, rg, ro;
        asm("mov.b64 {%0,%1},%2;" : "=f"(lo), "=f"(hi) : "l"(a0)); ri = gi + lo + hi;
        asm("mov.b64 {%0,%1},%2;" : "=f"(lo), "=f"(hi) : "l"(a1)); rf = gf + lo + hi;
        asm("mov.b64 {%0,%1},%2;" : "=f"(lo), "=f"(hi) : "l"(a2)); rg = gg + lo + hi;
        asm("mov.b64 {%0,%1},%2;" : "=f"(lo), "=f"(hi) : "l"(a3)); ro = go + lo + hi;
        float iv = fsig(ri);
        float fv = fsig(rf);
        float gv = ftanh(rg);
        float ov = fsig(ro);
        c = fv*c + iv*gv;
        float hval = ov*ftanh(c);
        g_H[1-buf][u][slot] = hval;
        if (t + 1 == mylen) g_Hsel[u][slot] = hval;
        int tn = (t + 1 < glen) ? (t + 1) : t;
        const float* gp = &g_G[tn][u][slot];
        gi = __ldcg(gp + 0);
        gf = __ldcg(gp + 256*128);
        gg = __ldcg(gp + 512*128);
        go = __ldcg(gp + 768*128);
        ep++;
        gridbar8(sg, ep << 4);
    }
}

__global__ void k_final(const float* W1, const float* b1, const float* W2, const float* b2,
                        const float* W3, const float* b3, float* out) {
    int b = blockIdx.x, pair = blockIdx.y, j = threadIdx.x;
    __shared__ float oa[NH], ob[NH], red[NH];
    int sa = g_slotOf[pair*64 + b], sb = g_slotOf[pair*64 + 32 + b];
    oa[j] = g_Hsel[j][sa]; ob[j] = g_Hsel[j][sb];
    __syncthreads();
    float u1 = b1[j], u2 = b2[j], u3 = b3[j];
    for (int k = 0; k < NH; k++) {
        float o = oa[k];
        u1 += o*W1[(size_t)j*NH+k];
        u2 += o*W2[(size_t)j*NH+k];
        u3 += o*W3[(size_t)j*NH+k];
    }
    float s1 = fsig(u1);
    float l2 = u2 >= 0.f ? u2 : 0.1f*u2;
    float cg = s1*l2;
    float s3 = fsig(u3);
    float lc = cg >= 0.f ? cg : 0.1f*cg;
    float fa = oa[j] + s3*lc;
    float d = fa - ob[j] + 1e-6f;
    red[j] = d*d;
    __syncthreads();
    for (int s = 128; s > 0; s >>= 1) { if (j < s) red[j] += red[j+s]; __syncthreads(); }
    if (j == 0) out[pair*32 + b] = expf(sqrtf(red[0]));
}

extern "C" void kernel_launch(void* const* d_in, const int* in_sizes, int n_in,
                              void* d_out, int out_size) {
    const float* anchor = (const float*)d_in[0];
    const float* trajs  = (const float*)d_in[1];
    const float* neg    = (const float*)d_in[2];
    const int* la = (const int*)d_in[3];
    const int* lt = (const int*)d_in[4];
    const int* ln = (const int*)d_in[5];
    const float* Wm  = (const float*)d_in[6];
    const float* bm  = (const float*)d_in[7];
    const float* Wih = (const float*)d_in[8];
    const float* Whh = (const float*)d_in[9];
    const float* bih = (const float*)d_in[10];
    const float* bhh = (const float*)d_in[11];
    const float* W1 = (const float*)d_in[12];
    const float* b1 = (const float*)d_in[13];
    const float* W2 = (const float*)d_in[14];
    const float* b2 = (const float*)d_in[15];
    const float* W3 = (const float*)d_in[16];
    const float* b3 = (const float*)d_in[17];
    float* out = (float*)d_out;

    static int rec_smem_set = 0;
    if (!rec_smem_set) {
        cudaFuncSetAttribute(k_rec, cudaFuncAttributeMaxDynamicSharedMemorySize, REC_SMEM);
        rec_smem_set = 1;
    }

    k_prep<<<1, 128>>>(la, lt, ln);
    k_feat<<<dim3(NT, NB, 3), 128>>>(anchor, trajs, neg, Wm, bm);
    k_scores<<<dim3(8, 8, 64), 256>>>();
    k_rowstats<<<dim3(NT, NB, 2), 128>>>();
    k_colstats<<<dim3(16, NB, 2), 256>>>();
    k_attnB<<<dim3(8, 1, 64), 256>>>();
    k_attnA<<<dim3(8, 1, 64), 256>>>();
    k_ingate<<<dim3(NT, 8, 2), 256>>>(Wih, bih, bhh);
    k_rec<<<128, 256, REC_SMEM>>>(Whh);
    k_final<<<dim3(NB, 2), 256>>>(W1, b1, W2, b2, W3, b3, out);
}

// round 17
// speedup vs baseline: 1.3326x; 1.0140x over previous
#include <cuda_runtime.h>
#include <math.h>

#define NT 512
#define NB 32
#define HF 128
#define NH 256

__device__ __align__(16) float g_feat[3][NB][NT][HF];
__device__ unsigned char g_mask[3][NB][NT];
__device__ __align__(16) float g_S[2][NB][NT][NT];
__device__ float g_rmax[2][NB][NT], g_rsum[2][NB][NT];
__device__ float g_cmax[2][NB][NT], g_csum[2][NB][NT];
__device__ __align__(16) float g_X[128][NT][NH];
__device__ __align__(16) float g_G[NT][1024][128];
__device__ __align__(16) float g_H[2][NH][128];
__device__ __align__(16) float g_Hsel[NH][128];
__device__ int g_lens[128], g_map[128], g_slotOf[128];
__device__ __align__(128) unsigned int g_cnt8[8][32];

__device__ __forceinline__ float fsig(float x) { return 1.f / (1.f + __expf(-x)); }
__device__ __forceinline__ float ftanh(float x) { return 2.f / (1.f + __expf(-2.f * x)) - 1.f; }

__global__ void k_prep(const int* la, const int* lt, const int* ln) {
    __shared__ int sl[128], si[128];
    int i = threadIdx.x, l = i >> 5, b = i & 31;
    int len = (l == 1) ? lt[b] : (l == 3) ? ln[b] : la[b];
    sl[i] = len; si[i] = i;
    __syncthreads();
    if (i == 0) {
        for (int a = 1; a < 128; a++) {
            int lv = sl[a], iv = si[a], c = a - 1;
            while (c >= 0 && sl[c] > lv) { sl[c+1]=sl[c]; si[c+1]=si[c]; c--; }
            sl[c+1]=lv; si[c+1]=iv;
        }
        for (int q = 0; q < 8; q++) g_cnt8[q][0] = 0u;
    }
    __syncthreads();
    g_lens[i] = sl[i]; g_map[i] = si[i]; g_slotOf[si[i]] = i;
}

__global__ void k_feat(const float* A, const float* T_, const float* N_,
                       const float* Wm, const float* bm) {
    int t = blockIdx.x, b = blockIdx.y, tr = blockIdx.z, j = threadIdx.x;
    const float* base = tr==0 ? A : (tr==1 ? T_ : N_);
    const float* x = base + ((size_t)b*NT + t)*4;
    float v = x[0]*Wm[2*j] + x[1]*Wm[2*j+1] + bm[j];
    float fv = v >= 0.f ? v : 0.1f*v;
    g_feat[tr][b][t][j] = fv;
    if (tr == 0) {
        g_X[g_slotOf[b]][t][j] = fv;
        g_X[g_slotOf[64 + b]][t][j] = fv;
    } else if (tr == 1) {
        g_X[g_slotOf[32 + b]][t][j] = fv;
    } else {
        g_X[g_slotOf[96 + b]][t][j] = fv;
    }
    if (j == 0) g_mask[tr][b][t] = (x[3]*128.f + x[2] - 257.f) > 0.5f ? 1 : 0;
}

// masked scores, 64 t x 128 s tile, packed f32x2 (ingate pattern)
__global__ void __launch_bounds__(256) k_scores() {
    int z = blockIdx.z, pair = z >> 5, b = z & 31;
    int t0 = blockIdx.x*64, s0 = blockIdx.y*128;
    __shared__ __align__(16) float As[16][68];    // [k][t]
    __shared__ __align__(16) float Bs[16][132];   // [k][s]
    int tid = threadIdx.x;
    int lrow = tid>>2, lq = tid&3;     // A: 64 t rows x 4 k-quads
    int brow = tid>>1;                 // B: 128 s rows
    int tx = tid&15, ty = tid>>4;
    unsigned long long acc[4][4];
    float fz = 0.f;
#pragma unroll
    for (int i=0;i<4;i++)
#pragma unroll
        for (int j=0;j<4;j++)
            asm("mov.b64 %0,{%1,%1};" : "=l"(acc[i][j]) : "f"(fz));

    const float* A = &g_feat[0][b][0][0];
    const float* Bf = &g_feat[1+pair][b][0][0];
    for (int k0 = 0; k0 < HF; k0 += 16) {
        float4 a4 = *(const float4*)(A + (size_t)(t0+lrow)*HF + k0 + lq*4);
        As[lq*4+0][lrow]=a4.x; As[lq*4+1][lrow]=a4.y; As[lq*4+2][lrow]=a4.z; As[lq*4+3][lrow]=a4.w;
#pragma unroll
        for (int p = 0; p < 2; p++) {
            int q = (tid&1)*2 + p;
            float4 b4 = *(const float4*)(Bf + (size_t)(s0+brow)*HF + k0 + q*4);
            Bs[q*4+0][brow]=b4.x; Bs[q*4+1][brow]=b4.y; Bs[q*4+2][brow]=b4.z; Bs[q*4+3][brow]=b4.w;
        }
        __syncthreads();
#pragma unroll
        for (int kk=0;kk<16;kk++) {
            float4 ra = *(const float4*)&As[kk][tx*4];
            ulonglong2 w1 = *(const ulonglong2*)&Bs[kk][ty*8];
            ulonglong2 w2 = *(const ulonglong2*)&Bs[kk][ty*8+4];
            float av[4] = {ra.x, ra.y, ra.z, ra.w};
#pragma unroll
            for (int i=0;i<4;i++) {
                unsigned long long h2;
                asm("mov.b64 %0,{%1,%1};" : "=l"(h2) : "f"(av[i]));
                asm("fma.rn.f32x2 %0,%1,%2,%0;" : "+l"(acc[i][0]) : "l"(h2), "l"(w1.x));
                asm("fma.rn.f32x2 %0,%1,%2,%0;" : "+l"(acc[i][1]) : "l"(h2), "l"(w1.y));
                asm("fma.rn.f32x2 %0,%1,%2,%0;" : "+l"(acc[i][2]) : "l"(h2), "l"(w2.x));
                asm("fma.rn.f32x2 %0,%1,%2,%0;" : "+l"(acc[i][3]) : "l"(h2), "l"(w2.y));
            }
        }
        __syncthreads();
    }
    bool mb[8];
#pragma unroll
    for (int j=0;j<8;j++) mb[j] = g_mask[1+pair][b][s0+ty*8+j] != 0;
#pragma unroll
    for (int i=0;i<4;i++) {
        int t = t0 + tx*4 + i;
        bool ma = g_mask[0][b][t] != 0;
        float v[8];
#pragma unroll
        for (int j = 0; j < 4; j++) {
            float lo, hi;
            asm("mov.b64 {%0,%1},%2;" : "=f"(lo), "=f"(hi) : "l"(acc[i][j]));
            v[j*2] = (ma && mb[j*2]) ? lo : -1e9f;
            v[j*2+1] = (ma && mb[j*2+1]) ? hi : -1e9f;
        }
        *(float4*)&g_S[pair][b][t][s0+ty*8] = make_float4(v[0],v[1],v[2],v[3]);
        *(float4*)&g_S[pair][b][t][s0+ty*8+4] = make_float4(v[4],v[5],v[6],v[7]);
    }
}

__global__ void k_rowstats() {
    int t = blockIdx.x, b = blockIdx.y, pair = blockIdx.z, tid = threadIdx.x;
    const float* row = &g_S[pair][b][t][0];
    float v0=row[tid], v1=row[tid+128], v2=row[tid+256], v3=row[tid+384];
    float m = fmaxf(fmaxf(v0,v1), fmaxf(v2,v3));
    __shared__ float red[128];
    red[tid]=m; __syncthreads();
    for (int s=64;s>0;s>>=1){ if(tid<s) red[tid]=fmaxf(red[tid],red[tid+s]); __syncthreads(); }
    m = red[0]; __syncthreads();
    float sm_ = __expf(v0-m)+__expf(v1-m)+__expf(v2-m)+__expf(v3-m);
    red[tid]=sm_; __syncthreads();
    for (int s=64;s>0;s>>=1){ if(tid<s) red[tid]+=red[tid+s]; __syncthreads(); }
    if (tid==0){ g_rmax[pair][b][t]=m; g_rsum[pair][b][t]=red[0]; }
}

__global__ void k_colstats() {
    int s0 = blockIdx.x*32, b = blockIdx.y, pair = blockIdx.z, tid = threadIdx.x;
    int tx = tid&31, ty = tid>>5;
    float m = -3e38f, sum = 0.f;
    for (int t = ty; t < NT; t += 8) {
        float v = g_S[pair][b][t][s0+tx];
        float nm = fmaxf(m, v);
        sum = sum*__expf(m-nm) + __expf(v-nm);
        m = nm;
    }
    __shared__ float sm_[8][32], ss_[8][32];
    sm_[ty][tx]=m; ss_[ty][tx]=sum;
    __syncthreads();
    if (ty==0) {
        float M=sm_[0][tx], S=ss_[0][tx];
#pragma unroll
        for (int w=1;w<8;w++) {
            float m2=sm_[w][tx], s2=ss_[w][tx];
            float nm=fmaxf(M,m2);
            S = S*__expf(M-nm) + s2*__expf(m2-nm);
            M = nm;
        }
        g_cmax[pair][b][s0+tx]=M; g_csum[pair][b][s0+tx]=S;
    }
}

__global__ void __launch_bounds__(256) k_attnB() {
    int z = blockIdx.z, pair = z>>5, b = z&31;
    int t0 = blockIdx.x*64;
    __shared__ __align__(16) float As[16][68];
    __shared__ __align__(16) float Bs[16][132];
    __shared__ float rm[64], rs[64];
    int tid = threadIdx.x;
    if (tid < 64) {
        float m = g_rmax[pair][b][t0+tid];
        rm[tid] = m;
        rs[tid] = (m > -1e8f) ? 1.f/g_rsum[pair][b][t0+tid] : 0.f;
    }
    __syncthreads();
    int lrow=tid>>2, lq=tid&3;
    int srow=tid>>4, jq=tid&15;
    int tx=tid&15, ty=tid>>4;
    unsigned long long acc[4][4];
    float fz = 0.f;
#pragma unroll
    for (int i=0;i<4;i++)
#pragma unroll
        for (int j=0;j<4;j++)
            asm("mov.b64 %0,{%1,%1};" : "=l"(acc[i][j]) : "f"(fz));
    for (int k0 = 0; k0 < NT; k0 += 16) {
        float4 a4 = *(const float4*)&g_S[pair][b][t0+lrow][k0+lq*4];
        float m = rm[lrow];
        As[lq*4+0][lrow]=__expf(a4.x-m); As[lq*4+1][lrow]=__expf(a4.y-m);
        As[lq*4+2][lrow]=__expf(a4.z-m); As[lq*4+3][lrow]=__expf(a4.w-m);
        float4 b1 = *(const float4*)&g_feat[1+pair][b][k0+srow][jq*4];
        float4 b2 = *(const float4*)&g_feat[1+pair][b][k0+srow][64+jq*4];
        Bs[srow][jq*4+0]=b1.x; Bs[srow][jq*4+1]=b1.y; Bs[srow][jq*4+2]=b1.z; Bs[srow][jq*4+3]=b1.w;
        Bs[srow][64+jq*4+0]=b2.x; Bs[srow][64+jq*4+1]=b2.y; Bs[srow][64+jq*4+2]=b2.z; Bs[srow][64+jq*4+3]=b2.w;
        __syncthreads();
#pragma unroll
        for (int kk=0;kk<16;kk++) {
            float4 ra = *(const float4*)&As[kk][tx*4];
            ulonglong2 w1 = *(const ulonglong2*)&Bs[kk][ty*8];
            ulonglong2 w2 = *(const ulonglong2*)&Bs[kk][ty*8+4];
            float av[4] = {ra.x, ra.y, ra.z, ra.w};
#pragma unroll
            for (int i=0;i<4;i++) {
                unsigned long long h2;
                asm("mov.b64 %0,{%1,%1};" : "=l"(h2) : "f"(av[i]));
                asm("fma.rn.f32x2 %0,%1,%2,%0;" : "+l"(acc[i][0]) : "l"(h2), "l"(w1.x));
                asm("fma.rn.f32x2 %0,%1,%2,%0;" : "+l"(acc[i][1]) : "l"(h2), "l"(w1.y));
                asm("fma.rn.f32x2 %0,%1,%2,%0;" : "+l"(acc[i][2]) : "l"(h2), "l"(w2.x));
                asm("fma.rn.f32x2 %0,%1,%2,%0;" : "+l"(acc[i][3]) : "l"(h2), "l"(w2.y));
            }
        }
        __syncthreads();
    }
    int slot = g_slotOf[pair*64 + b];
#pragma unroll
    for (int i=0;i<4;i++) {
        int t = t0 + tx*4 + i;
        float sc = rs[tx*4+i];
        float v[8];
#pragma unroll
        for (int j = 0; j < 4; j++) {
            float lo, hi;
            asm("mov.b64 {%0,%1},%2;" : "=f"(lo), "=f"(hi) : "l"(acc[i][j]));
            v[j*2] = lo; v[j*2+1] = hi;
        }
        float4 f1 = *(const float4*)&g_feat[0][b][t][ty*8];
        float4 f2 = *(const float4*)&g_feat[0][b][t][ty*8+4];
        *(float4*)&g_X[slot][t][HF + ty*8] =
            make_float4(f1.x-v[0]*sc, f1.y-v[1]*sc, f1.z-v[2]*sc, f1.w-v[3]*sc);
        *(float4*)&g_X[slot][t][HF + ty*8+4] =
            make_float4(f2.x-v[4]*sc, f2.y-v[5]*sc, f2.z-v[6]*sc, f2.w-v[7]*sc);
    }
}

__global__ void __launch_bounds__(256) k_attnA() {
    int z = blockIdx.z, pair = z>>5, b = z&31;
    int s0 = blockIdx.x*64;
    __shared__ __align__(16) float As[16][68];
    __shared__ __align__(16) float Bs[16][132];
    __shared__ float cm[64], cs[64];
    int tid = threadIdx.x;
    if (tid < 64) {
        float m = g_cmax[pair][b][s0+tid];
        cm[tid] = m;
        cs[tid] = (m > -1e8f) ? 1.f/g_csum[pair][b][s0+tid] : 0.f;
    }
    __syncthreads();
    int r = tid>>4, q = tid&15;
    int tx = tid&15, ty = tid>>4;
    unsigned long long acc[4][4];
    float fz = 0.f;
#pragma unroll
    for (int i=0;i<4;i++)
#pragma unroll
        for (int j=0;j<4;j++)
            asm("mov.b64 %0,{%1,%1};" : "=l"(acc[i][j]) : "f"(fz));
    for (int k0 = 0; k0 < NT; k0 += 16) {
        float4 a4 = *(const float4*)&g_S[pair][b][k0+r][s0+q*4];
        As[r][q*4+0]=__expf(a4.x-cm[q*4+0]); As[r][q*4+1]=__expf(a4.y-cm[q*4+1]);
        As[r][q*4+2]=__expf(a4.z-cm[q*4+2]); As[r][q*4+3]=__expf(a4.w-cm[q*4+3]);
        float4 b1 = *(const float4*)&g_feat[0][b][k0+r][q*4];
        float4 b2 = *(const float4*)&g_feat[0][b][k0+r][64+q*4];
        Bs[r][q*4+0]=b1.x; Bs[r][q*4+1]=b1.y; Bs[r][q*4+2]=b1.z; Bs[r][q*4+3]=b1.w;
        Bs[r][64+q*4+0]=b2.x; Bs[r][64+q*4+1]=b2.y; Bs[r][64+q*4+2]=b2.z; Bs[r][64+q*4+3]=b2.w;
        __syncthreads();
#pragma unroll
        for (int kk=0;kk<16;kk++) {
            float4 ra = *(const float4*)&As[kk][tx*4];
            ulonglong2 w1 = *(const ulonglong2*)&Bs[kk][ty*8];
            ulonglong2 w2 = *(const ulonglong2*)&Bs[kk][ty*8+4];
            float av[4] = {ra.x, ra.y, ra.z, ra.w};
#pragma unroll
            for (int i=0;i<4;i++) {
                unsigned long long h2;
                asm("mov.b64 %0,{%1,%1};" : "=l"(h2) : "f"(av[i]));
                asm("fma.rn.f32x2 %0,%1,%2,%0;" : "+l"(acc[i][0]) : "l"(h2), "l"(w1.x));
                asm("fma.rn.f32x2 %0,%1,%2,%0;" : "+l"(acc[i][1]) : "l"(h2), "l"(w1.y));
                asm("fma.rn.f32x2 %0,%1,%2,%0;" : "+l"(acc[i][2]) : "l"(h2), "l"(w2.x));
                asm("fma.rn.f32x2 %0,%1,%2,%0;" : "+l"(acc[i][3]) : "l"(h2), "l"(w2.y));
            }
        }
        __syncthreads();
    }
    int slot = g_slotOf[pair*64 + 32 + b];
#pragma unroll
    for (int i=0;i<4;i++) {
        int s = s0 + tx*4 + i;
        float sc = cs[tx*4+i];
        float v[8];
#pragma unroll
        for (int j = 0; j < 4; j++) {
            float lo, hi;
            asm("mov.b64 {%0,%1},%2;" : "=f"(lo), "=f"(hi) : "l"(acc[i][j]));
            v[j*2] = lo; v[j*2+1] = hi;
        }
        float4 f1 = *(const float4*)&g_feat[1+pair][b][s][ty*8];
        float4 f2 = *(const float4*)&g_feat[1+pair][b][s][ty*8+4];
        *(float4*)&g_X[slot][s][HF + ty*8] =
            make_float4(f1.x-v[0]*sc, f1.y-v[1]*sc, f1.z-v[2]*sc, f1.w-v[3]*sc);
        *(float4*)&g_X[slot][s][HF + ty*8+4] =
            make_float4(f2.x-v[4]*sc, f2.y-v[5]*sc, f2.z-v[6]*sc, f2.w-v[7]*sc);
    }
}

__global__ void __launch_bounds__(256) k_ingate(const float* __restrict__ Wih,
                                                const float* __restrict__ bih,
                                                const float* __restrict__ bhh) {
    int t = blockIdx.x, n0 = blockIdx.y*128, s0 = blockIdx.z*64;
    if (t >= g_lens[s0+63]) return;
    __shared__ __align__(16) float As[16][68];
    __shared__ __align__(16) float Bs[16][132];
    int tid = threadIdx.x;
    int arow = tid>>2, aq = tid&3;
    int brow = tid>>1;
    int tx = tid&15, ty = tid>>4;
    unsigned long long acc[4][4];
    float fz = 0.f;
#pragma unroll
    for (int i=0;i<4;i++)
#pragma unroll
        for (int j=0;j<4;j++)
            asm("mov.b64 %0,{%1,%1};" : "=l"(acc[i][j]) : "f"(fz));

    for (int k0 = 0; k0 < NH; k0 += 16) {
        float4 a4 = *(const float4*)&g_X[s0+arow][t][k0 + aq*4];
        As[aq*4+0][arow]=a4.x; As[aq*4+1][arow]=a4.y; As[aq*4+2][arow]=a4.z; As[aq*4+3][arow]=a4.w;
#pragma unroll
        for (int p = 0; p < 2; p++) {
            int q = (tid&1)*2 + p;
            float4 b4 = *(const float4*)(Wih + (size_t)(n0+brow)*NH + k0 + q*4);
            Bs[q*4+0][brow]=b4.x; Bs[q*4+1][brow]=b4.y; Bs[q*4+2][brow]=b4.z; Bs[q*4+3][brow]=b4.w;
        }
        __syncthreads();
#pragma unroll
        for (int kk=0;kk<16;kk++) {
            float4 ra = *(const float4*)&As[kk][tx*4];
            ulonglong2 w1 = *(const ulonglong2*)&Bs[kk][ty*8];
            ulonglong2 w2 = *(const ulonglong2*)&Bs[kk][ty*8+4];
            float av[4] = {ra.x, ra.y, ra.z, ra.w};
#pragma unroll
            for (int i=0;i<4;i++) {
                unsigned long long h2;
                asm("mov.b64 %0,{%1,%1};" : "=l"(h2) : "f"(av[i]));
                asm("fma.rn.f32x2 %0,%1,%2,%0;" : "+l"(acc[i][0]) : "l"(h2), "l"(w1.x));
                asm("fma.rn.f32x2 %0,%1,%2,%0;" : "+l"(acc[i][1]) : "l"(h2), "l"(w1.y));
                asm("fma.rn.f32x2 %0,%1,%2,%0;" : "+l"(acc[i][2]) : "l"(h2), "l"(w2.x));
                asm("fma.rn.f32x2 %0,%1,%2,%0;" : "+l"(acc[i][3]) : "l"(h2), "l"(w2.y));
            }
        }
        __syncthreads();
    }
#pragma unroll
    for (int j = 0; j < 8; j++) {
        int n = n0 + ty*8 + j;
        float bs = bih[n] + bhh[n];
        float v[4];
#pragma unroll
        for (int i = 0; i < 4; i++) {
            float lo, hi;
            asm("mov.b64 {%0,%1},%2;" : "=f"(lo), "=f"(hi) : "l"(acc[i][j>>1]));
            v[i] = ((j & 1) ? hi : lo) + bs;
        }
        *(float4*)&g_G[t][n][s0 + tx*4] = make_float4(v[0], v[1], v[2], v[3]);
    }
}

// acquire/release barrier: red.release arrival, bare ld.acquire spin (no nanosleep)
__device__ __forceinline__ void gridbar8(int sg, unsigned int target) {
    __syncthreads();
    if (threadIdx.x == 0) {
        unsigned int* cp = &g_cnt8[sg][0];
        asm volatile("red.release.gpu.global.add.u32 [%0], 1;" :: "l"(cp) : "memory");
        unsigned int v;
        do {
            asm volatile("ld.acquire.gpu.global.u32 %0, [%1];" : "=r"(v) : "l"(cp) : "memory");
        } while (v < target);
    }
    __syncthreads();
}

// 128 CTAs: 16 unit-groups (16 units each) x 8 slot-groups (16 slots each).
#define REC_SMEM ((16384 + 4096) * 4 + 1024)

__global__ void __launch_bounds__(256, 1) k_rec(const float* __restrict__ Whh) {
    extern __shared__ float sh[];
    float* w_s = sh;           // [k(256)][uu(16)][gate(4)]  64 KB
    float* h_s = sh + 16384;   // [k(256)][sl(16)]           16 KB
    int tid = threadIdx.x;
    int ug = blockIdx.x >> 3;
    int sg = blockIdx.x & 7;
    int u0 = ug * 16, s0 = sg * 16;

    for (int i = tid; i < 16384; i += 256) {
        int k = i >> 6, r = i & 63, uu = r >> 2, g = r & 3;
        w_s[i] = Whh[(size_t)((g << 8) + u0 + uu)*256 + k];
    }

    int w = tid >> 5, lane = tid & 31;
    int uu = (w << 1) + (lane >> 4);
    int sl = lane & 15;
    int u = u0 + uu, slot = s0 + sl;
    int mylen = g_lens[slot];
    int glen = g_lens[s0 + 15];
    float c = 0.f;
    g_H[0][u][slot] = 0.f;
    unsigned int ep = 1;
    gridbar8(sg, ep << 4);

    const float* gbase = &g_G[0][u][slot];
    float gi = __ldcg(gbase + 0);
    float gf = __ldcg(gbase + 256*128);
    float gg = __ldcg(gbase + 512*128);
    float go = __ldcg(gbase + 768*128);

    for (int t = 0; t < glen; t++) {
        int buf = t & 1;
#pragma unroll
        for (int p = 0; p < 4; p++) {
            int idx = tid + (p << 8);
            int k = idx >> 2, f4 = idx & 3;
            float4 v = __ldcg((const float4*)&g_H[buf][k][s0 + f4*4]);
            *(float4*)&h_s[(k << 4) + (f4 << 2)] = v;
        }
        __syncthreads();
        unsigned long long aif, ago, h2;
        asm("mov.b64 %0,{%1,%2};" : "=l"(aif) : "f"(gi), "f"(gf));
        asm("mov.b64 %0,{%1,%2};" : "=l"(ago) : "f"(gg), "f"(go));
        const float* wp = w_s + uu*4;
        const float* hp = h_s + sl;
#pragma unroll 8
        for (int k = 0; k < 256; k++) {
            float hv = hp[k << 4];
            ulonglong2 w2 = *(const ulonglong2*)(wp + (k << 6));
            asm("mov.b64 %0,{%1,%1};" : "=l"(h2) : "f"(hv));
            asm("fma.rn.f32x2 %0,%1,%2,%0;" : "+l"(aif) : "l"(h2), "l"(w2.x));
            asm("fma.rn.f32x2 %0,%1,%2,%0;" : "+l"(ago) : "l"(h2), "l"(w2.y));
        }
        float ri, rf, rg, ro;
        asm("mov.b64 {%0,%1},%2;" : "=f"(ri), "=f"(rf) : "l"(aif));
        asm("mov.b64 {%0,%1},%2;" : "=f"(rg), "=f"(ro) : "l"(ago));
        float iv = fsig(ri);
        float fv = fsig(rf);
        float gv = ftanh(rg);
        float ov = fsig(ro);
        c = fv*c + iv*gv;
        float hval = ov*ftanh(c);
        g_H[1-buf][u][slot] = hval;
        if (t + 1 == mylen) g_Hsel[u][slot] = hval;
        int tn = (t + 1 < glen) ? (t + 1) : t;
        const float* gp = &g_G[tn][u][slot];
        gi = __ldcg(gp + 0);
        gf = __ldcg(gp + 256*128);
        gg = __ldcg(gp + 512*128);
        go = __ldcg(gp + 768*128);
        ep++;
        gridbar8(sg, ep << 4);
    }
}

__global__ void k_final(const float* W1, const float* b1, const float* W2, const float* b2,
                        const float* W3, const float* b3, float* out) {
    int b = blockIdx.x, pair = blockIdx.y, j = threadIdx.x;
    __shared__ float oa[NH], ob[NH], red[NH];
    int sa = g_slotOf[pair*64 + b], sb = g_slotOf[pair*64 + 32 + b];
    oa[j] = g_Hsel[j][sa]; ob[j] = g_Hsel[j][sb];
    __syncthreads();
    float u1 = b1[j], u2 = b2[j], u3 = b3[j];
    for (int k = 0; k < NH; k++) {
        float o = oa[k];
        u1 += o*W1[(size_t)j*NH+k];
        u2 += o*W2[(size_t)j*NH+k];
        u3 += o*W3[(size_t)j*NH+k];
    }
    float s1 = fsig(u1);
    float l2 = u2 >= 0.f ? u2 : 0.1f*u2;
    float cg = s1*l2;
    float s3 = fsig(u3);
    float lc = cg >= 0.f ? cg : 0.1f*cg;
    float fa = oa[j] + s3*lc;
    float d = fa - ob[j] + 1e-6f;
    red[j] = d*d;
    __syncthreads();
    for (int s = 128; s > 0; s >>= 1) { if (j < s) red[j] += red[j+s]; __syncthreads(); }
    if (j == 0) out[pair*32 + b] = expf(sqrtf(red[0]));
}

extern "C" void kernel_launch(void* const* d_in, const int* in_sizes, int n_in,
                              void* d_out, int out_size) {
    const float* anchor = (const float*)d_in[0];
    const float* trajs  = (const float*)d_in[1];
    const float* neg    = (const float*)d_in[2];
    const int* la = (const int*)d_in[3];
    const int* lt = (const int*)d_in[4];
    const int* ln = (const int*)d_in[5];
    const float* Wm  = (const float*)d_in[6];
    const float* bm  = (const float*)d_in[7];
    const float* Wih = (const float*)d_in[8];
    const float* Whh = (const float*)d_in[9];
    const float* bih = (const float*)d_in[10];
    const float* bhh = (const float*)d_in[11];
    const float* W1 = (const float*)d_in[12];
    const float* b1 = (const float*)d_in[13];
    const float* W2 = (const float*)d_in[14];
    const float* b2 = (const float*)d_in[15];
    const float* W3 = (const float*)d_in[16];
    const float* b3 = (const float*)d_in[17];
    float* out = (float*)d_out;

    static int rec_smem_set = 0;
    if (!rec_smem_set) {
        cudaFuncSetAttribute(k_rec, cudaFuncAttributeMaxDynamicSharedMemorySize, REC_SMEM);
        rec_smem_set = 1;
    }

    k_prep<<<1, 128>>>(la, lt, ln);
    k_feat<<<dim3(NT, NB, 3), 128>>>(anchor, trajs, neg, Wm, bm);
    k_scores<<<dim3(8, 4, 64), 256>>>();
    k_rowstats<<<dim3(NT, NB, 2), 128>>>();
    k_colstats<<<dim3(16, NB, 2), 256>>>();
    k_attnB<<<dim3(8, 1, 64), 256>>>();
    k_attnA<<<dim3(8, 1, 64), 256>>>();
    k_ingate<<<dim3(NT, 8, 2), 256>>>(Wih, bih, bhh);
    k_rec<<<128, 256, REC_SMEM>>>(Whh);
    k_final<<<dim3(NB, 2), 256>>>(W1, b1, W2, b2, W3, b3, out);
}